// round 12
// baseline (speedup 1.0000x reference)
#include <cuda_runtime.h>

// Capsule routing layer — persistent-CTA grid-stride, s32-redux fixed point,
// fully unrolled core (sm_100). 592 CTAs; each processes ~n/592 nodes.
// Per node: warp = capsule k, lane = neighbor m; z / ub / u packed f32x2 in
// registers; u replicated across lanes at 2^21 fixed-point scale (cancels in
// p = z.u_hat via il; descaled at store). Next node's neighbor index is
// prefetched during the current node's routing loop.

static __device__ __forceinline__ int redux_add_s32(int v) {
    int r;
    asm("redux.sync.add.s32 %0, %1, 0xffffffff;" : "=r"(r) : "r"(v));
    return r;
}
static __device__ __forceinline__ unsigned long long pack2(float lo, float hi) {
    unsigned long long r;
    asm("mov.b64 %0, {%1, %2};" : "=l"(r) : "f"(lo), "f"(hi));
    return r;
}
static __device__ __forceinline__ void unpack2(unsigned long long v, float& lo, float& hi) {
    asm("mov.b64 {%0, %1}, %2;" : "=f"(lo), "=f"(hi) : "l"(v));
}
static __device__ __forceinline__ unsigned long long fma2(
    unsigned long long a, unsigned long long b, unsigned long long c) {
    unsigned long long r;
    asm("fma.rn.f32x2 %0, %1, %2, %3;" : "=l"(r) : "l"(a), "l"(b), "l"(c));
    return r;
}
static __device__ __forceinline__ unsigned long long add2(
    unsigned long long a, unsigned long long b) {
    unsigned long long r;
    asm("add.rn.f32x2 %0, %1, %2;" : "=l"(r) : "l"(a), "l"(b));
    return r;
}
static __device__ __forceinline__ float ex2f(float x) {
    float r; asm("ex2.approx.f32 %0, %1;" : "=f"(r) : "f"(x)); return r;
}
static __device__ __forceinline__ float rsqf(float x) {
    float r; asm("rsqrt.approx.f32 %0, %1;" : "=f"(r) : "f"(x)); return r;
}
static __device__ __forceinline__ float rcpf(float x) {
    float r; asm("rcp.approx.f32 %0, %1;" : "=f"(r) : "f"(x)); return r;
}

constexpr float S21   = 2097152.0f;              // 2^21 phase-B fixed point
constexpr float IS21  = 1.0f / 2097152.0f;
constexpr float S20   = 1048576.0f;              // 2^20 exp-sum fixed point
constexpr float LOG2E = 1.4426950408889634f;

template <int UNROLL_N>
static __device__ __forceinline__ void routing_core(
    const unsigned long long zp[8], const unsigned long long ubs[8],
    unsigned long long up[8],
    float (*e_sh)[36], int lane, int k, float param, float q1, float w0,
    int max_iter)
{
    const float C1 = param * (S20 * S21);   // a1 = C1 * e / smf
    const float C2 = q1 * S21;              // w  = a1 + C2 * e / sk
    float il = 0.f;                          // rsqrt(||u_fix||^2) * log2(e)
    float* e_w0 = &e_sh[lane][0];
    float* e_w1 = &e_sh[32 + lane][0];

    const int trip = UNROLL_N > 0 ? UNROLL_N : max_iter;
    #pragma unroll
    for (int it = 0; it < trip; ++it) {
        float w;
        if (it == 0) {
            w = w0 * S21;                            // p = 0 -> uniform softmaxes
        } else {
            // ---- pre-barrier: dot, exp, STS, neighbor-softmax half ----
            unsigned long long pp = 0ull;
            #pragma unroll
            for (int j = 0; j < 8; ++j) pp = fma2(zp[j], up[j], pp);
            float plo, phi; unpack2(pp, plo, phi);
            const float e = ex2f((plo + phi) * il);  // exp(p/||u||), |.|<=1

            float* ew = (it & 1) ? e_w1 : e_w0;
            ew[k] = e;                               // STS (pre-barrier)

            const int ei = __float2int_rn(e * S20);
            const float smf = (float)redux_add_s32(ei);   // S20*sum_m e (exact)
            const float a1 = (C1 * e) * rcpf(smf);
            const float a2 = C2 * e;

            __syncthreads();
            // ---- post-barrier: capsule-softmax half, merged weight ----
            const float4 ea = *reinterpret_cast<const float4*>(ew);
            const float4 eb = *reinterpret_cast<const float4*>(ew + 4);
            const unsigned long long s =
                add2(add2(pack2(ea.x, ea.y), pack2(ea.z, ea.w)),
                     add2(pack2(eb.x, eb.y), pack2(eb.z, eb.w)));
            float s0, s1; unpack2(s, s0, s1);
            w = fmaf(a2, rcpf(s0 + s1), a1);         // already at 2^21 scale
        }

        // ---- phase B: t = w*z + ub; exact integer redux over neighbors ----
        const unsigned long long ws2 = pack2(w, w);
        const bool last = (it + 1 >= trip);
        unsigned long long ss2 = 0ull;
        #pragma unroll
        for (int j = 0; j < 8; ++j) {
            const unsigned long long t = fma2(ws2, zp[j], ubs[j]);
            float f0, f1; unpack2(t, f0, f1);
            const float u0 = (float)redux_add_s32(__float2int_rn(f0));
            const float u1 = (float)redux_add_s32(__float2int_rn(f1));
            up[j] = pack2(u0, u1);
            if (!last) ss2 = fma2(up[j], up[j], ss2);
        }
        if (!last) {
            float slo, shi; unpack2(ss2, slo, shi);
            il = rsqf(fmaxf(slo + shi, 1e-20f)) * LOG2E;
        }
    }
}

__global__ __launch_bounds__(256, 4)
void routing_kernel(const float* __restrict__ x,
                    const int*   __restrict__ nbrs,
                    const float* __restrict__ param_p,
                    const int*   __restrict__ miter_p,
                    float*       __restrict__ out,
                    int n)
{
    constexpr int DIM = 128, DD = 16, M = 32;

    __shared__ __align__(16) float e_sh[2 * M][36];  // padded rows, float4-readable

    const int tid  = threadIdx.x;
    const int k    = tid >> 5;     // warp = capsule
    const int lane = tid & 31;     // lane = neighbor m

    const float param = *param_p;
    int max_iter = *miter_p;
    if (max_iter < 1 || max_iter > 1000) {           // defensive scalar decode
        float f = __int_as_float(max_iter);
        max_iter = (f >= 1.0f && f <= 1000.0f) ? (int)f : 6;
    }

    const float q1 = 1.0f - param;
    const float w0 = param * (1.0f / 32.0f) + q1 * (1.0f / 8.0f);
    const int stride = gridDim.x;

    int node = blockIdx.x;
    // prefetch first neighbor index
    int idx = (node < n) ? nbrs[node * M + lane] : 0;

    for (; node < n; node += stride) {
        const int cur_idx = idx;

        // ---- own features: normalize, scale to 2^21/32, keep packed ----
        unsigned long long ubs[8];
        {
            const float4* src = reinterpret_cast<const float4*>(
                x + (size_t)node * DIM + k * DD);
            float4 t0 = src[0], t1 = src[1], t2 = src[2], t3 = src[3];
            float v[DD] = {t0.x,t0.y,t0.z,t0.w, t1.x,t1.y,t1.z,t1.w,
                           t2.x,t2.y,t2.z,t2.w, t3.x,t3.y,t3.z,t3.w};
            float ss = 0.f;
            #pragma unroll
            for (int d = 0; d < DD; ++d) ss = fmaf(v[d], v[d], ss);
            const float sc = (S21 / 32.0f) * rsqf(fmaxf(ss, 1e-24f));
            #pragma unroll
            for (int j = 0; j < 8; ++j) ubs[j] = pack2(v[2*j] * sc, v[2*j+1] * sc);
        }

        // ---- gather neighbor capsule row, L2-normalize, keep packed ----
        unsigned long long zp[8];
        {
            float z[DD];
            if ((unsigned)cur_idx < (unsigned)n) {
                const float4* src = reinterpret_cast<const float4*>(
                    x + (size_t)cur_idx * DIM + k * DD);
                float4 t0 = src[0], t1 = src[1], t2 = src[2], t3 = src[3];
                z[0]=t0.x; z[1]=t0.y; z[2]=t0.z; z[3]=t0.w;
                z[4]=t1.x; z[5]=t1.y; z[6]=t1.z; z[7]=t1.w;
                z[8]=t2.x; z[9]=t2.y; z[10]=t2.z; z[11]=t2.w;
                z[12]=t3.x; z[13]=t3.y; z[14]=t3.z; z[15]=t3.w;
                float ss = 0.f;
                #pragma unroll
                for (int d = 0; d < DD; ++d) ss = fmaf(z[d], z[d], ss);
                const float sc = rsqf(fmaxf(ss, 1e-24f));
                #pragma unroll
                for (int d = 0; d < DD; ++d) z[d] *= sc;
            } else {
                #pragma unroll
                for (int d = 0; d < DD; ++d) z[d] = 0.f;
            }
            #pragma unroll
            for (int j = 0; j < 8; ++j) zp[j] = pack2(z[2*j], z[2*j+1]);
        }

        // ---- prefetch next node's neighbor index (hidden by routing loop) ----
        const int next = node + stride;
        if (next < n) idx = nbrs[next * M + lane];

        unsigned long long up[8];    // u at 2^21 scale, replicated, packed
        if (max_iter == 6) {
            routing_core<6>(zp, ubs, up, e_sh, lane, k, param, q1, w0, 6);
        } else {
            routing_core<0>(zp, ubs, up, e_sh, lane, k, param, q1, w0, max_iter);
        }

        // every lane holds the full result; lane 0 of each warp writes 64B
        if (lane == 0) {
            float uo[DD];
            #pragma unroll
            for (int j = 0; j < 8; ++j) {
                float a, b; unpack2(up[j], a, b);
                uo[2*j] = a * IS21; uo[2*j+1] = b * IS21;
            }
            float4* dst = reinterpret_cast<float4*>(out + (size_t)node * DIM + k * DD);
            dst[0] = make_float4(uo[0],  uo[1],  uo[2],  uo[3]);
            dst[1] = make_float4(uo[4],  uo[5],  uo[6],  uo[7]);
            dst[2] = make_float4(uo[8],  uo[9],  uo[10], uo[11]);
            dst[3] = make_float4(uo[12], uo[13], uo[14], uo[15]);
        }
        // next trip's barrier (iteration 1 of the core) orders e_sh reuse;
        // no extra __syncthreads needed here: e_sh writes happen pre-barrier
        // and reads post-barrier within each iteration, and the first write of
        // the next node targets buffer 1 while the last read of this node was
        // ordered by this node's final barrier.
        __syncthreads();
    }
}

extern "C" void kernel_launch(void* const* d_in, const int* in_sizes, int n_in,
                              void* d_out, int out_size)
{
    const float* x     = (const float*)d_in[0];
    const int*   nbrs  = (const int*)d_in[1];
    const float* param = (const float*)d_in[2];
    const int*   miter = (const int*)d_in[3];
    float*       out   = (float*)d_out;

    const int n = in_sizes[0] / 128;
    int blocks = 592;                      // 148 SMs x 4 resident CTAs
    if (blocks > n) blocks = n;
    routing_kernel<<<blocks, 256>>>(x, nbrs, param, miter, out, n);
}

// round 13
// speedup vs baseline: 1.2119x; 1.2119x over previous
#include <cuda_runtime.h>

// Capsule routing layer — s32-redux fixed point, fully unrolled (sm_100).
// 1 block (256 thr) per node; warp = capsule k, lane = neighbor m.
// z / ub / u packed f32x2 in registers; u replicated across lanes at 2^21
// fixed-point scale (cancels in p = z.u_hat via il; descaled at store).
// Long-latency scalar work (F2I/REDUX/rcp for the neighbor softmax) sits
// BEFORE __syncthreads (barrier-skew shadow); phase B runs once with the
// merged weight w = a1 + a2/sk. Neighbor index load issued first (it heads
// the 2-hop LDG->LDG gather chain).

static __device__ __forceinline__ int redux_add_s32(int v) {
    int r;
    asm("redux.sync.add.s32 %0, %1, 0xffffffff;" : "=r"(r) : "r"(v));
    return r;
}
static __device__ __forceinline__ unsigned long long pack2(float lo, float hi) {
    unsigned long long r;
    asm("mov.b64 %0, {%1, %2};" : "=l"(r) : "f"(lo), "f"(hi));
    return r;
}
static __device__ __forceinline__ void unpack2(unsigned long long v, float& lo, float& hi) {
    asm("mov.b64 {%0, %1}, %2;" : "=f"(lo), "=f"(hi) : "l"(v));
}
static __device__ __forceinline__ unsigned long long fma2(
    unsigned long long a, unsigned long long b, unsigned long long c) {
    unsigned long long r;
    asm("fma.rn.f32x2 %0, %1, %2, %3;" : "=l"(r) : "l"(a), "l"(b), "l"(c));
    return r;
}
static __device__ __forceinline__ unsigned long long add2(
    unsigned long long a, unsigned long long b) {
    unsigned long long r;
    asm("add.rn.f32x2 %0, %1, %2;" : "=l"(r) : "l"(a), "l"(b));
    return r;
}
static __device__ __forceinline__ float ex2f(float x) {
    float r; asm("ex2.approx.f32 %0, %1;" : "=f"(r) : "f"(x)); return r;
}
static __device__ __forceinline__ float rsqf(float x) {
    float r; asm("rsqrt.approx.f32 %0, %1;" : "=f"(r) : "f"(x)); return r;
}
static __device__ __forceinline__ float rcpf(float x) {
    float r; asm("rcp.approx.f32 %0, %1;" : "=f"(r) : "f"(x)); return r;
}

constexpr float S21   = 2097152.0f;              // 2^21 phase-B fixed point
constexpr float IS21  = 1.0f / 2097152.0f;
constexpr float S20   = 1048576.0f;              // 2^20 exp-sum fixed point
constexpr float LOG2E = 1.4426950408889634f;

template <int UNROLL_N>
static __device__ __forceinline__ void routing_core(
    const unsigned long long zp[8], const unsigned long long ubs[8],
    unsigned long long up[8],
    float (*e_sh)[36], int lane, int k, float param, float q1, float w0,
    int max_iter)
{
    const float C1 = param * (S20 * S21);   // a1 = C1 * e / smf
    const float C2 = q1 * S21;              // w  = a1 + C2 * e / sk
    float il = 0.f;                          // rsqrt(||u_fix||^2) * log2(e)
    float* e_w0 = &e_sh[lane][0];
    float* e_w1 = &e_sh[32 + lane][0];

    const int trip = UNROLL_N > 0 ? UNROLL_N : max_iter;
    #pragma unroll
    for (int it = 0; it < trip; ++it) {
        float w;
        if (it == 0) {
            w = w0 * S21;                            // p = 0 -> uniform softmaxes
        } else {
            // ---- pre-barrier: dot, exp, STS, neighbor-softmax half ----
            unsigned long long pp = 0ull;
            #pragma unroll
            for (int j = 0; j < 8; ++j) pp = fma2(zp[j], up[j], pp);
            float plo, phi; unpack2(pp, plo, phi);
            const float e = ex2f((plo + phi) * il);  // exp(p/||u||), |.|<=1

            float* ew = (it & 1) ? e_w1 : e_w0;
            ew[k] = e;                               // STS (pre-barrier)

            const int ei = __float2int_rn(e * S20);
            const float smf = (float)redux_add_s32(ei);   // S20*sum_m e (exact)
            const float a1 = (C1 * e) * rcpf(smf);
            const float a2 = C2 * e;

            __syncthreads();
            // ---- post-barrier: capsule-softmax half, merged weight ----
            const float4 ea = *reinterpret_cast<const float4*>(ew);
            const float4 eb = *reinterpret_cast<const float4*>(ew + 4);
            const unsigned long long s =
                add2(add2(pack2(ea.x, ea.y), pack2(ea.z, ea.w)),
                     add2(pack2(eb.x, eb.y), pack2(eb.z, eb.w)));
            float s0, s1; unpack2(s, s0, s1);
            w = fmaf(a2, rcpf(s0 + s1), a1);         // already at 2^21 scale
        }

        // ---- phase B: t = w*z + ub; exact integer redux over neighbors ----
        const unsigned long long ws2 = pack2(w, w);
        const bool last = (it + 1 >= trip);
        unsigned long long ss2 = 0ull;
        #pragma unroll
        for (int j = 0; j < 8; ++j) {
            const unsigned long long t = fma2(ws2, zp[j], ubs[j]);
            float f0, f1; unpack2(t, f0, f1);
            const float u0 = (float)redux_add_s32(__float2int_rn(f0));
            const float u1 = (float)redux_add_s32(__float2int_rn(f1));
            up[j] = pack2(u0, u1);
            if (!last) ss2 = fma2(up[j], up[j], ss2);
        }
        if (!last) {
            float slo, shi; unpack2(ss2, slo, shi);
            il = rsqf(fmaxf(slo + shi, 1e-20f)) * LOG2E;
        }
    }
}

__global__ __launch_bounds__(256, 4)
void routing_kernel(const float* __restrict__ x,
                    const int*   __restrict__ nbrs,
                    const float* __restrict__ param_p,
                    const int*   __restrict__ miter_p,
                    float*       __restrict__ out,
                    int n)
{
    constexpr int DIM = 128, DD = 16, M = 32;

    __shared__ __align__(16) float e_sh[2 * M][36];  // padded rows, float4-readable

    const int node = blockIdx.x;
    const int tid  = threadIdx.x;
    const int k    = tid >> 5;     // warp = capsule
    const int lane = tid & 31;     // lane = neighbor m

    // issue the 2-hop gather chain head FIRST
    const int idx = nbrs[node * M + lane];

    const float param = *param_p;
    int max_iter = *miter_p;
    if (max_iter < 1 || max_iter > 1000) {           // defensive scalar decode
        float f = __int_as_float(max_iter);
        max_iter = (f >= 1.0f && f <= 1000.0f) ? (int)f : 6;
    }

    // ---- gather neighbor capsule row, L2-normalize, keep packed ----
    unsigned long long zp[8];
    {
        float z[DD];
        if ((unsigned)idx < (unsigned)n) {
            const float4* src = reinterpret_cast<const float4*>(x + (size_t)idx * DIM + k * DD);
            float4 t0 = src[0], t1 = src[1], t2 = src[2], t3 = src[3];
            z[0]=t0.x; z[1]=t0.y; z[2]=t0.z; z[3]=t0.w;
            z[4]=t1.x; z[5]=t1.y; z[6]=t1.z; z[7]=t1.w;
            z[8]=t2.x; z[9]=t2.y; z[10]=t2.z; z[11]=t2.w;
            z[12]=t3.x; z[13]=t3.y; z[14]=t3.z; z[15]=t3.w;
            float ss = 0.f;
            #pragma unroll
            for (int d = 0; d < DD; ++d) ss = fmaf(z[d], z[d], ss);
            const float sc = rsqf(fmaxf(ss, 1e-24f));
            #pragma unroll
            for (int d = 0; d < DD; ++d) z[d] *= sc;
        } else {
            #pragma unroll
            for (int d = 0; d < DD; ++d) z[d] = 0.f;
        }
        #pragma unroll
        for (int j = 0; j < 8; ++j) zp[j] = pack2(z[2*j], z[2*j+1]);
    }

    // ---- own features: normalize, scale to 2^21/32, keep packed ----
    unsigned long long ubs[8];
    {
        const float4* src = reinterpret_cast<const float4*>(x + (size_t)node * DIM + k * DD);
        float4 t0 = src[0], t1 = src[1], t2 = src[2], t3 = src[3];
        float v[DD] = {t0.x,t0.y,t0.z,t0.w, t1.x,t1.y,t1.z,t1.w,
                       t2.x,t2.y,t2.z,t2.w, t3.x,t3.y,t3.z,t3.w};
        float ss = 0.f;
        #pragma unroll
        for (int d = 0; d < DD; ++d) ss = fmaf(v[d], v[d], ss);
        const float sc = (S21 / 32.0f) * rsqf(fmaxf(ss, 1e-24f));
        #pragma unroll
        for (int j = 0; j < 8; ++j) ubs[j] = pack2(v[2*j] * sc, v[2*j+1] * sc);
    }

    unsigned long long up[8];    // u at 2^21 scale, replicated, packed
    const float q1 = 1.0f - param;
    const float w0 = param * (1.0f / 32.0f) + q1 * (1.0f / 8.0f);

    if (max_iter == 6) {
        routing_core<6>(zp, ubs, up, e_sh, lane, k, param, q1, w0, 6);
    } else {
        routing_core<0>(zp, ubs, up, e_sh, lane, k, param, q1, w0, max_iter);
    }

    // every lane holds the full result; lane 0 of each warp writes 64B
    if (lane == 0) {
        float uo[DD];
        #pragma unroll
        for (int j = 0; j < 8; ++j) {
            float a, b; unpack2(up[j], a, b);
            uo[2*j] = a * IS21; uo[2*j+1] = b * IS21;
        }
        float4* dst = reinterpret_cast<float4*>(out + (size_t)node * DIM + k * DD);
        dst[0] = make_float4(uo[0],  uo[1],  uo[2],  uo[3]);
        dst[1] = make_float4(uo[4],  uo[5],  uo[6],  uo[7]);
        dst[2] = make_float4(uo[8],  uo[9],  uo[10], uo[11]);
        dst[3] = make_float4(uo[12], uo[13], uo[14], uo[15]);
    }
}

extern "C" void kernel_launch(void* const* d_in, const int* in_sizes, int n_in,
                              void* d_out, int out_size)
{
    const float* x     = (const float*)d_in[0];
    const int*   nbrs  = (const int*)d_in[1];
    const float* param = (const float*)d_in[2];
    const int*   miter = (const int*)d_in[3];
    float*       out   = (float*)d_out;

    const int n = in_sizes[0] / 128;
    routing_kernel<<<n, 256>>>(x, nbrs, param, miter, out, n);
}

// round 14
// speedup vs baseline: 1.2254x; 1.0112x over previous
#include <cuda_runtime.h>

// Capsule routing layer — s32-redux fixed point, fully unrolled (sm_100).
// 1 block (256 thr) per node; warp = capsule k, lane = neighbor m.
// z / ub / u packed f32x2 in registers; u replicated across lanes at 2^21
// fixed-point scale (cancels in p = z.u_hat via il; descaled at store).
// Long-latency scalar work (F2I/REDUX/rcp for the neighbor softmax) is placed
// BEFORE __syncthreads so it executes in the barrier-skew shadow; phase B runs
// once with the merged weight w = a1 + a2/sk.
// [R14 = exact re-land of the R9 measured optimum.]

static __device__ __forceinline__ int redux_add_s32(int v) {
    int r;
    asm("redux.sync.add.s32 %0, %1, 0xffffffff;" : "=r"(r) : "r"(v));
    return r;
}
static __device__ __forceinline__ unsigned long long pack2(float lo, float hi) {
    unsigned long long r;
    asm("mov.b64 %0, {%1, %2};" : "=l"(r) : "f"(lo), "f"(hi));
    return r;
}
static __device__ __forceinline__ void unpack2(unsigned long long v, float& lo, float& hi) {
    asm("mov.b64 {%0, %1}, %2;" : "=f"(lo), "=f"(hi) : "l"(v));
}
static __device__ __forceinline__ unsigned long long fma2(
    unsigned long long a, unsigned long long b, unsigned long long c) {
    unsigned long long r;
    asm("fma.rn.f32x2 %0, %1, %2, %3;" : "=l"(r) : "l"(a), "l"(b), "l"(c));
    return r;
}
static __device__ __forceinline__ unsigned long long add2(
    unsigned long long a, unsigned long long b) {
    unsigned long long r;
    asm("add.rn.f32x2 %0, %1, %2;" : "=l"(r) : "l"(a), "l"(b));
    return r;
}
static __device__ __forceinline__ float ex2f(float x) {
    float r; asm("ex2.approx.f32 %0, %1;" : "=f"(r) : "f"(x)); return r;
}
static __device__ __forceinline__ float rsqf(float x) {
    float r; asm("rsqrt.approx.f32 %0, %1;" : "=f"(r) : "f"(x)); return r;
}
static __device__ __forceinline__ float rcpf(float x) {
    float r; asm("rcp.approx.f32 %0, %1;" : "=f"(r) : "f"(x)); return r;
}

constexpr float S21   = 2097152.0f;              // 2^21 phase-B fixed point
constexpr float IS21  = 1.0f / 2097152.0f;
constexpr float S20   = 1048576.0f;              // 2^20 exp-sum fixed point
constexpr float LOG2E = 1.4426950408889634f;

template <int UNROLL_N>
static __device__ __forceinline__ void routing_core(
    const unsigned long long zp[8], const unsigned long long ubs[8],
    unsigned long long up[8],
    float (*e_sh)[36], int lane, int k, float param, float q1, float w0,
    int max_iter)
{
    const float C1 = param * (S20 * S21);   // a1 = C1 * e / smf
    const float C2 = q1 * S21;              // w  = a1 + C2 * e / sk
    float il = 0.f;                          // rsqrt(||u_fix||^2) * log2(e)
    float* e_w0 = &e_sh[lane][0];
    float* e_w1 = &e_sh[32 + lane][0];

    const int trip = UNROLL_N > 0 ? UNROLL_N : max_iter;
    #pragma unroll
    for (int it = 0; it < trip; ++it) {
        float w;
        if (it == 0) {
            w = w0 * S21;                            // p = 0 -> uniform softmaxes
        } else {
            // ---- pre-barrier: dot, exp, STS, neighbor-softmax half ----
            unsigned long long pp = 0ull;
            #pragma unroll
            for (int j = 0; j < 8; ++j) pp = fma2(zp[j], up[j], pp);
            float plo, phi; unpack2(pp, plo, phi);
            const float e = ex2f((plo + phi) * il);  // exp(p/||u||), |.|<=1

            float* ew = (it & 1) ? e_w1 : e_w0;
            ew[k] = e;                               // STS (pre-barrier)

            const int ei = __float2int_rn(e * S20);
            const float smf = (float)redux_add_s32(ei);   // S20*sum_m e (exact)
            const float a1 = (C1 * e) * rcpf(smf);
            const float a2 = C2 * e;

            __syncthreads();
            // ---- post-barrier: capsule-softmax half, merged weight ----
            const float4 ea = *reinterpret_cast<const float4*>(ew);
            const float4 eb = *reinterpret_cast<const float4*>(ew + 4);
            const unsigned long long s =
                add2(add2(pack2(ea.x, ea.y), pack2(ea.z, ea.w)),
                     add2(pack2(eb.x, eb.y), pack2(eb.z, eb.w)));
            float s0, s1; unpack2(s, s0, s1);
            w = fmaf(a2, rcpf(s0 + s1), a1);         // already at 2^21 scale
        }

        // ---- phase B: t = w*z + ub; exact integer redux over neighbors ----
        const unsigned long long ws2 = pack2(w, w);
        const bool last = (it + 1 >= trip);
        unsigned long long ss2 = 0ull;
        #pragma unroll
        for (int j = 0; j < 8; ++j) {
            const unsigned long long t = fma2(ws2, zp[j], ubs[j]);
            float f0, f1; unpack2(t, f0, f1);
            const float u0 = (float)redux_add_s32(__float2int_rn(f0));
            const float u1 = (float)redux_add_s32(__float2int_rn(f1));
            up[j] = pack2(u0, u1);
            if (!last) ss2 = fma2(up[j], up[j], ss2);
        }
        if (!last) {
            float slo, shi; unpack2(ss2, slo, shi);
            il = rsqf(fmaxf(slo + shi, 1e-20f)) * LOG2E;
        }
    }
}

__global__ __launch_bounds__(256, 4)
void routing_kernel(const float* __restrict__ x,
                    const int*   __restrict__ nbrs,
                    const float* __restrict__ param_p,
                    const int*   __restrict__ miter_p,
                    float*       __restrict__ out,
                    int n)
{
    constexpr int DIM = 128, DD = 16, M = 32;

    __shared__ __align__(16) float e_sh[2 * M][36];  // padded rows, float4-readable

    const int node = blockIdx.x;
    const int tid  = threadIdx.x;
    const int k    = tid >> 5;     // warp = capsule
    const int lane = tid & 31;     // lane = neighbor m

    const float param = *param_p;
    int max_iter = *miter_p;
    if (max_iter < 1 || max_iter > 1000) {           // defensive scalar decode
        float f = __int_as_float(max_iter);
        max_iter = (f >= 1.0f && f <= 1000.0f) ? (int)f : 6;
    }

    // ---- own features: normalize, scale to 2^21/32, keep packed ----
    unsigned long long ubs[8];
    {
        const float4* src = reinterpret_cast<const float4*>(x + (size_t)node * DIM + k * DD);
        float4 t0 = src[0], t1 = src[1], t2 = src[2], t3 = src[3];
        float v[DD] = {t0.x,t0.y,t0.z,t0.w, t1.x,t1.y,t1.z,t1.w,
                       t2.x,t2.y,t2.z,t2.w, t3.x,t3.y,t3.z,t3.w};
        float ss = 0.f;
        #pragma unroll
        for (int d = 0; d < DD; ++d) ss = fmaf(v[d], v[d], ss);
        const float sc = (S21 / 32.0f) * rsqf(fmaxf(ss, 1e-24f));
        #pragma unroll
        for (int j = 0; j < 8; ++j) ubs[j] = pack2(v[2*j] * sc, v[2*j+1] * sc);
    }

    // ---- gather neighbor capsule row, L2-normalize, keep packed ----
    unsigned long long zp[8];
    {
        const int idx = nbrs[node * M + lane];
        float z[DD];
        if ((unsigned)idx < (unsigned)n) {
            const float4* src = reinterpret_cast<const float4*>(x + (size_t)idx * DIM + k * DD);
            float4 t0 = src[0], t1 = src[1], t2 = src[2], t3 = src[3];
            z[0]=t0.x; z[1]=t0.y; z[2]=t0.z; z[3]=t0.w;
            z[4]=t1.x; z[5]=t1.y; z[6]=t1.z; z[7]=t1.w;
            z[8]=t2.x; z[9]=t2.y; z[10]=t2.z; z[11]=t2.w;
            z[12]=t3.x; z[13]=t3.y; z[14]=t3.z; z[15]=t3.w;
            float ss = 0.f;
            #pragma unroll
            for (int d = 0; d < DD; ++d) ss = fmaf(z[d], z[d], ss);
            const float sc = rsqf(fmaxf(ss, 1e-24f));
            #pragma unroll
            for (int d = 0; d < DD; ++d) z[d] *= sc;
        } else {
            #pragma unroll
            for (int d = 0; d < DD; ++d) z[d] = 0.f;
        }
        #pragma unroll
        for (int j = 0; j < 8; ++j) zp[j] = pack2(z[2*j], z[2*j+1]);
    }

    unsigned long long up[8];    // u at 2^21 scale, replicated, packed
    const float q1 = 1.0f - param;
    const float w0 = param * (1.0f / 32.0f) + q1 * (1.0f / 8.0f);

    if (max_iter == 6) {
        routing_core<6>(zp, ubs, up, e_sh, lane, k, param, q1, w0, 6);
    } else {
        routing_core<0>(zp, ubs, up, e_sh, lane, k, param, q1, w0, max_iter);
    }

    // every lane holds the full result; lane 0 of each warp writes 64B
    if (lane == 0) {
        float uo[DD];
        #pragma unroll
        for (int j = 0; j < 8; ++j) {
            float a, b; unpack2(up[j], a, b);
            uo[2*j] = a * IS21; uo[2*j+1] = b * IS21;
        }
        float4* dst = reinterpret_cast<float4*>(out + (size_t)node * DIM + k * DD);
        dst[0] = make_float4(uo[0],  uo[1],  uo[2],  uo[3]);
        dst[1] = make_float4(uo[4],  uo[5],  uo[6],  uo[7]);
        dst[2] = make_float4(uo[8],  uo[9],  uo[10], uo[11]);
        dst[3] = make_float4(uo[12], uo[13], uo[14], uo[15]);
    }
}

extern "C" void kernel_launch(void* const* d_in, const int* in_sizes, int n_in,
                              void* d_out, int out_size)
{
    const float* x     = (const float*)d_in[0];
    const int*   nbrs  = (const int*)d_in[1];
    const float* param = (const float*)d_in[2];
    const int*   miter = (const int*)d_in[3];
    float*       out   = (float*)d_out;

    const int n = in_sizes[0] / 128;
    routing_kernel<<<n, 256>>>(x, nbrs, param, miter, out, n);
}